// round 6
// baseline (speedup 1.0000x reference)
#include <cuda_runtime.h>
#include <cuda_bf16.h>
#include <cstdint>

// Problem constants
#define NNODES 100000
#define DDIM   128
#define RREL   3
#define EEDGES 500000
#define NBASIS 2
#define RN     (RREL * NNODES)
#define RE     (RREL * EEDGES)

// ---------------- scratch (device globals) ----------------------------------
__device__ float g_h0[(size_t)NNODES * DDIM];
__device__ float g_h1[(size_t)NNODES * DDIM];
__device__ __nv_bfloat16 g_h0hi[(size_t)NNODES * DDIM];
__device__ __nv_bfloat16 g_h0lo[(size_t)NNODES * DDIM];
__device__ __nv_bfloat16 g_h1hi[(size_t)NNODES * DDIM];
__device__ __nv_bfloat16 g_h1lo[(size_t)NNODES * DDIM];
__device__ __nv_bfloat16 g_c0hi[(size_t)NNODES * DDIM];
__device__ __nv_bfloat16 g_c0lo[(size_t)NNODES * DDIM];
__device__ __nv_bfloat16 g_c1hi[(size_t)NNODES * DDIM];
__device__ __nv_bfloat16 g_c1lo[(size_t)NNODES * DDIM];
__device__ float g_rdeg[RN];
__device__ int   g_deg [RN];
__device__ int   g_off [RN + 1];
__device__ int   g_cur [RN];
__device__ int   g_part[1024];
__device__ int   g_csr [RE];
__device__ __nv_bfloat16 g_wthi[128 * 384];
__device__ __nv_bfloat16 g_wtlo[128 * 384];
__device__ __nv_bfloat16 g_pwhi[128 * 128];
__device__ __nv_bfloat16 g_pwlo[128 * 128];

// ---------------- smem layout for the GEMM -----------------------------------
// A buffer (per chunk, 36864 B):
//   F32A path : fp32 [128 x 64], pitch 288 B
//   plane path: bf16 hi [128 x 64] pitch 144 B at +0, lo at +18432
// B buffer: bf16 hi/lo [128 x 64], pitch 144 B each.
#define A_TILE 36864
#define B_PITCH 144
#define B_TILE (128 * B_PITCH)                 // 18432
#define OFF_A0 0
#define OFF_A1 (A_TILE)
#define OFF_BHI (2 * A_TILE)
#define OFF_BLO (2 * A_TILE + B_TILE)
#define GEMM_SMEM (2 * A_TILE + 2 * B_TILE)    // 110592

__device__ __forceinline__ uint32_t smem_u32(const void* p) {
    uint32_t a;
    asm("{ .reg .u64 t; cvta.to.shared.u64 t, %1; cvt.u32.u64 %0, t; }" : "=r"(a) : "l"(p));
    return a;
}

__device__ __forceinline__ void cp_async16(uint32_t dst, const void* src, uint32_t sz) {
    asm volatile("cp.async.cg.shared.global [%0], [%1], 16, %2;"
                 :: "r"(dst), "l"(src), "r"(sz));
}
#define CP_COMMIT()  asm volatile("cp.async.commit_group;" ::: "memory")
#define CP_WAIT(n)   asm volatile("cp.async.wait_group %0;" :: "n"(n) : "memory")

__device__ __forceinline__ void mma16816(float* c, const uint32_t* a, const uint32_t* b) {
    asm volatile(
        "mma.sync.aligned.m16n8k16.row.col.f32.bf16.bf16.f32 "
        "{%0,%1,%2,%3}, {%4,%5,%6,%7}, {%8,%9}, {%0,%1,%2,%3};\n"
        : "+f"(c[0]), "+f"(c[1]), "+f"(c[2]), "+f"(c[3])
        : "r"(a[0]), "r"(a[1]), "r"(a[2]), "r"(a[3]), "r"(b[0]), "r"(b[1]));
}

// fp32 pair -> packed bf16x2 hi + packed bf16x2 residual(lo). x -> low half.
__device__ __forceinline__ void split2(float2 f, uint32_t& h, uint32_t& l) {
    uint32_t hh;
    asm("cvt.rn.bf16x2.f32 %0, %1, %2;" : "=r"(hh) : "f"(f.y), "f"(f.x));
    float h0 = __uint_as_float(hh << 16);
    float h1 = __uint_as_float(hh & 0xffff0000u);
    asm("cvt.rn.bf16x2.f32 %0, %1, %2;" : "=r"(l) : "f"(f.y - h1), "f"(f.x - h0));
    h = hh;
}

// ---------------- split-bf16 tensor-core GEMM ---------------------------------
// F32A:   A = single fp32 segment Af (split in-loop).      NSEG must be 1.
// !F32A:  A = NSEG bf16 hi/lo plane segments (pre-split).
// PLANES: epilogue also writes bf16 hi/lo planes of C.
template <bool RELU, int NSEG, bool F32A, bool PLANES>
__global__ __launch_bounds__(256, 2)
void tc_gemm(const float* __restrict__ Af,
             const __nv_bfloat16* __restrict__ P0h, const __nv_bfloat16* __restrict__ P0l,
             const __nv_bfloat16* __restrict__ P1h, const __nv_bfloat16* __restrict__ P1l,
             const __nv_bfloat16* __restrict__ P2h, const __nv_bfloat16* __restrict__ P2l,
             const __nv_bfloat16* __restrict__ whi, const __nv_bfloat16* __restrict__ wlo,
             const float* __restrict__ bias, float* __restrict__ C,
             __nv_bfloat16* __restrict__ Chi, __nv_bfloat16* __restrict__ Clo, int nrows) {
    extern __shared__ char smem[];
    const uint32_t sbase = smem_u32(smem);
    const int tid  = threadIdx.x;
    const int wid  = tid >> 5;
    const int lane = tid & 31;
    const int wm = wid & 3;
    const int wn = wid >> 2;
    const int g  = lane >> 2;
    const int tg = lane & 3;
    const int n0 = blockIdx.x * 128;
    const int KSTRIDE = NSEG * 128;
    const __nv_bfloat16* Ph[3] = {P0h, P1h, P2h};
    const __nv_bfloat16* Pl[3] = {P0l, P1l, P2l};
    const int NCHUNK = 2 * NSEG;

    float acc[2][8][4];
#pragma unroll
    for (int mt = 0; mt < 2; mt++)
#pragma unroll
        for (int nt = 0; nt < 8; nt++)
#pragma unroll
            for (int j = 0; j < 4; j++) acc[mt][nt][j] = 0.f;

    auto load_A = [&](int cc) {
        const int kc = (cc & 1) * 64;
        uint32_t dbase = sbase + ((cc & 1) ? OFF_A1 : OFF_A0);
        if constexpr (F32A) {
#pragma unroll
            for (int i = 0; i < 8; ++i) {
                int idx = i * 256 + tid;              // 2048 x 16B
                int row = idx >> 4;
                int q   = idx & 15;
                int n = n0 + row;
                bool valid = (n < nrows);
                const float* src = Af + (size_t)(valid ? n : 0) * DDIM + kc + q * 4;
                cp_async16(dbase + row * 288 + q * 16, src, valid ? 16u : 0u);
            }
        } else {
            const int seg = cc >> 1;
            const __nv_bfloat16* sh = Ph[seg];
            const __nv_bfloat16* sl = Pl[seg];
#pragma unroll
            for (int i = 0; i < 8; ++i) {
                int idx = i * 256 + tid;              // 2048 x 16B, 1024 per plane
                int plane = idx >> 10;
                int row = (idx >> 3) & 127;
                int q   = idx & 7;
                int n = n0 + row;
                bool valid = (n < nrows);
                const __nv_bfloat16* base = plane ? sl : sh;
                const __nv_bfloat16* src = base + (size_t)(valid ? n : 0) * DDIM + kc + q * 8;
                cp_async16(dbase + plane * B_TILE + row * B_PITCH + q * 16, src, valid ? 16u : 0u);
            }
        }
    };

    auto load_B = [&](int cc) {
#pragma unroll
        for (int i = 0; i < 4; ++i) {
            int idx = i * 256 + tid;
            int n = idx >> 3;
            int q = idx & 7;
            uint32_t boff = n * B_PITCH + q * 16;
            size_t goff = (size_t)n * KSTRIDE + cc * 64 + q * 8;
            cp_async16(sbase + OFF_BHI + boff, whi + goff, 16);
            cp_async16(sbase + OFF_BLO + boff, wlo + goff, 16);
        }
    };

    const int arow_f = (wm * 32 + g) * 72 + 2 * tg;          // fp32 path (float idx)
    const int arow_b = (wm * 32 + g) * B_PITCH + tg * 4;     // plane path (byte)
    const int brow   = (wn * 64 + g) * B_PITCH + tg * 4;

    load_A(0);
    CP_COMMIT();

#pragma unroll 1
    for (int c = 0; c < NCHUNK; ++c) {
        load_B(c);
        CP_COMMIT();
        if (c + 1 < NCHUNK) {
            load_A(c + 1);
            CP_COMMIT();
            CP_WAIT(1);
        } else {
            CP_WAIT(0);
        }
        __syncthreads();

        const char* Ab = smem + ((c & 1) ? OFF_A1 : OFF_A0);

#pragma unroll
        for (int ks = 0; ks < 4; ++ks) {
            uint32_t ahi[2][4], alo[2][4], bfr[8][2];
            if constexpr (F32A) {
#pragma unroll
                for (int mt = 0; mt < 2; ++mt) {
                    int fb = arow_f + mt * 16 * 72 + ks * 16;
                    float2 f0 = *reinterpret_cast<const float2*>(Ab + fb * 4);
                    float2 f1 = *reinterpret_cast<const float2*>(Ab + (fb + 8 * 72) * 4);
                    float2 f2 = *reinterpret_cast<const float2*>(Ab + (fb + 8) * 4);
                    float2 f3 = *reinterpret_cast<const float2*>(Ab + (fb + 8 * 72 + 8) * 4);
                    split2(f0, ahi[mt][0], alo[mt][0]);
                    split2(f1, ahi[mt][1], alo[mt][1]);
                    split2(f2, ahi[mt][2], alo[mt][2]);
                    split2(f3, ahi[mt][3], alo[mt][3]);
                }
            } else {
#pragma unroll
                for (int mt = 0; mt < 2; ++mt) {
                    int bb = arow_b + mt * 16 * B_PITCH + ks * 32;
                    ahi[mt][0] = *(const uint32_t*)(Ab + bb);
                    ahi[mt][1] = *(const uint32_t*)(Ab + bb + 8 * B_PITCH);
                    ahi[mt][2] = *(const uint32_t*)(Ab + bb + 16);
                    ahi[mt][3] = *(const uint32_t*)(Ab + bb + 8 * B_PITCH + 16);
                    alo[mt][0] = *(const uint32_t*)(Ab + B_TILE + bb);
                    alo[mt][1] = *(const uint32_t*)(Ab + B_TILE + bb + 8 * B_PITCH);
                    alo[mt][2] = *(const uint32_t*)(Ab + B_TILE + bb + 16);
                    alo[mt][3] = *(const uint32_t*)(Ab + B_TILE + bb + 8 * B_PITCH + 16);
                }
            }
#pragma unroll
            for (int nt = 0; nt < 8; ++nt) {
                int bb = brow + nt * (8 * B_PITCH) + ks * 32;
                bfr[nt][0] = *(const uint32_t*)(smem + OFF_BHI + bb);
                bfr[nt][1] = *(const uint32_t*)(smem + OFF_BHI + bb + 16);
            }
#pragma unroll
            for (int mt = 0; mt < 2; ++mt)
#pragma unroll
                for (int nt = 0; nt < 8; ++nt) {
                    mma16816(acc[mt][nt], ahi[mt], bfr[nt]);   // hi*hi
                    mma16816(acc[mt][nt], alo[mt], bfr[nt]);   // lo*hi
                }
#pragma unroll
            for (int nt = 0; nt < 8; ++nt) {
                int bb = brow + nt * (8 * B_PITCH) + ks * 32;
                bfr[nt][0] = *(const uint32_t*)(smem + OFF_BLO + bb);
                bfr[nt][1] = *(const uint32_t*)(smem + OFF_BLO + bb + 16);
            }
#pragma unroll
            for (int mt = 0; mt < 2; ++mt)
#pragma unroll
                for (int nt = 0; nt < 8; ++nt)
                    mma16816(acc[mt][nt], ahi[mt], bfr[nt]);   // hi*lo
        }
        __syncthreads();
    }

    // ---- epilogue: bias + relu, fp32 stores (+ optional bf16 plane stores) ----
#pragma unroll
    for (int nt = 0; nt < 8; ++nt) {
        int col = wn * 64 + nt * 8 + 2 * tg;
        float bz0 = __ldg(bias + col);
        float bz1 = __ldg(bias + col + 1);
#pragma unroll
        for (int mt = 0; mt < 2; ++mt) {
            int row0 = n0 + wm * 32 + mt * 16 + g;
            int row1 = row0 + 8;
            float v0 = acc[mt][nt][0] + bz0, v1 = acc[mt][nt][1] + bz1;
            float v2 = acc[mt][nt][2] + bz0, v3 = acc[mt][nt][3] + bz1;
            if (RELU) {
                v0 = fmaxf(v0, 0.f); v1 = fmaxf(v1, 0.f);
                v2 = fmaxf(v2, 0.f); v3 = fmaxf(v3, 0.f);
            }
            if (row0 < nrows) {
                *reinterpret_cast<float2*>(C + (size_t)row0 * DDIM + col) = make_float2(v0, v1);
                if constexpr (PLANES) {
                    uint32_t h, l;
                    split2(make_float2(v0, v1), h, l);
                    reinterpret_cast<uint32_t*>(Chi)[(size_t)row0 * (DDIM / 2) + col / 2] = h;
                    reinterpret_cast<uint32_t*>(Clo)[(size_t)row0 * (DDIM / 2) + col / 2] = l;
                }
            }
            if (row1 < nrows) {
                *reinterpret_cast<float2*>(C + (size_t)row1 * DDIM + col) = make_float2(v2, v3);
                if constexpr (PLANES) {
                    uint32_t h, l;
                    split2(make_float2(v2, v3), h, l);
                    reinterpret_cast<uint32_t*>(Chi)[(size_t)row1 * (DDIM / 2) + col / 2] = h;
                    reinterpret_cast<uint32_t*>(Clo)[(size_t)row1 * (DDIM / 2) + col / 2] = l;
                }
            }
        }
    }
}

// ---------------- CSR construction -------------------------------------------
__global__ void zero_int_kernel(int* p, int n) {
    int i = blockIdx.x * blockDim.x + threadIdx.x;
    if (i < n) p[i] = 0;
}

__global__ void deg_count_kernel(const int* __restrict__ dst, int* __restrict__ deg) {
    int i = blockIdx.x * blockDim.x + threadIdx.x;
    if (i >= RE) return;
    int r = i / EEDGES;
    atomicAdd(&deg[r * NNODES + dst[i]], 1);
}

__global__ void scan_reduce(const int* __restrict__ deg, int* __restrict__ part, int n) {
    __shared__ int sm[256];
    int b = blockIdx.x, t = threadIdx.x;
    int i0 = b * 1024 + t * 4;
    int s = 0;
#pragma unroll
    for (int j = 0; j < 4; ++j) { int i = i0 + j; if (i < n) s += deg[i]; }
    sm[t] = s; __syncthreads();
    for (int st = 128; st > 0; st >>= 1) { if (t < st) sm[t] += sm[t + st]; __syncthreads(); }
    if (t == 0) part[b] = sm[0];
}

__global__ void scan_partials(int* part, int n) {
    __shared__ int sm[512];
    int t = threadIdx.x;
    int v = (t < n) ? part[t] : 0;
    sm[t] = v; __syncthreads();
    for (int s = 1; s < 512; s <<= 1) {
        int add = (t >= s) ? sm[t - s] : 0;
        __syncthreads();
        sm[t] += add;
        __syncthreads();
    }
    if (t < n) part[t] = sm[t] - v;
}

// final scan -> off, cur, rdeg; off[RN] = RE
__global__ void scan_final(const int* __restrict__ deg, const int* __restrict__ part,
                           int* __restrict__ off, int* __restrict__ cur,
                           float* __restrict__ rdeg, int n) {
    __shared__ int sm[256];
    int b = blockIdx.x, t = threadIdx.x;
    if (b == 0 && t == 0) off[RN] = RE;
    int i0 = b * 1024 + t * 4;
    int v[4]; int s = 0;
#pragma unroll
    for (int j = 0; j < 4; ++j) { int i = i0 + j; v[j] = (i < n) ? deg[i] : 0; s += v[j]; }
    sm[t] = s; __syncthreads();
    for (int st = 1; st < 256; st <<= 1) {
        int add = (t >= st) ? sm[t - st] : 0;
        __syncthreads();
        sm[t] += add;
        __syncthreads();
    }
    int base = part[b] + sm[t] - s;
#pragma unroll
    for (int j = 0; j < 4; ++j) {
        int i = i0 + j;
        if (i < n) {
            off[i] = base; cur[i] = base; base += v[j];
            rdeg[i] = 1.0f / fmaxf((float)v[j], 1.0f);
        }
    }
}

// fill CSR + build proj weights (extra blocks)
#define FILL_BLOCKS ((RE + 255) / 256)
__global__ void fill_csr_wt(const int* __restrict__ src, const int* __restrict__ dst,
                            int* __restrict__ cur, int* __restrict__ csr,
                            const float* __restrict__ projw,
                            __nv_bfloat16* __restrict__ pwhi, __nv_bfloat16* __restrict__ pwlo) {
    int b = blockIdx.x;
    if (b >= FILL_BLOCKS) {
        int i = (b - FILL_BLOCKS) * 256 + threadIdx.x;   // 128*128
        if (i < 128 * 128) {
            int o = i >> 7;
            int k = i & 127;
            float v = projw[k * DDIM + o];
            __nv_bfloat16 h = __float2bfloat16(v);
            pwhi[i] = h;
            pwlo[i] = __float2bfloat16(v - __bfloat162float(h));
        }
        return;
    }
    int i = b * 256 + threadIdx.x;
    if (i >= RE) return;
    int r = i / EEDGES;
    int slot = atomicAdd(&cur[r * NNODES + dst[i]], 1);
    csr[slot] = src[i];
}

// ---------------- gather-aggregate into bf16-split basis combos + wt build ----
#define GATHER_BLOCKS ((NNODES * 32 + 255) / 256)
__global__ __launch_bounds__(256)
void gather_combo_wt(const float* __restrict__ h, const int* __restrict__ off,
                     const int* __restrict__ csr, const float* __restrict__ rdeg,
                     const float* __restrict__ coeff,
                     __nv_bfloat16* __restrict__ c0hi, __nv_bfloat16* __restrict__ c0lo,
                     __nv_bfloat16* __restrict__ c1hi, __nv_bfloat16* __restrict__ c1lo,
                     const float* __restrict__ basis, const float* __restrict__ loopw,
                     __nv_bfloat16* __restrict__ whi, __nv_bfloat16* __restrict__ wlo) {
    int b = blockIdx.x;
    if (b >= GATHER_BLOCKS) {
        int i = (b - GATHER_BLOCKS) * 256 + threadIdx.x;   // 128*384
        if (i < 128 * 384) {
            int o = i / 384;
            int k = i - o * 384;
            int seg = k >> 7;
            int kk = k & 127;
            float v = (seg < 2) ? basis[(size_t)seg * DDIM * DDIM + kk * DDIM + o]
                                : loopw[kk * DDIM + o];
            __nv_bfloat16 hh = __float2bfloat16(v);
            whi[i] = hh;
            wlo[i] = __float2bfloat16(v - __bfloat162float(hh));
        }
        return;
    }
    int gw = (int)(((unsigned)b * 256u + threadIdx.x) >> 5);
    int lane = threadIdx.x & 31;
    if (gw >= NNODES) return;
    float4 a0 = make_float4(0.f, 0.f, 0.f, 0.f);
    float4 a1 = a0;
#pragma unroll
    for (int r = 0; r < RREL; ++r) {
        int base = r * NNODES + gw;
        int s0 = __ldg(off + base), s1 = __ldg(off + base + 1);
        float4 sum = make_float4(0.f, 0.f, 0.f, 0.f);
        int e = s0;
        for (; e + 2 <= s1; e += 2) {
            int sa = __ldg(csr + e), sb = __ldg(csr + e + 1);
            float4 va = *reinterpret_cast<const float4*>(h + (size_t)sa * DDIM + lane * 4);
            float4 vb = *reinterpret_cast<const float4*>(h + (size_t)sb * DDIM + lane * 4);
            sum.x += va.x + vb.x; sum.y += va.y + vb.y;
            sum.z += va.z + vb.z; sum.w += va.w + vb.w;
        }
        if (e < s1) {
            int sa = __ldg(csr + e);
            float4 va = *reinterpret_cast<const float4*>(h + (size_t)sa * DDIM + lane * 4);
            sum.x += va.x; sum.y += va.y; sum.z += va.z; sum.w += va.w;
        }
        float w  = __ldg(rdeg + base);
        float k0 = __ldg(coeff + r * NBASIS)     * w;
        float k1 = __ldg(coeff + r * NBASIS + 1) * w;
        a0.x += k0 * sum.x; a0.y += k0 * sum.y; a0.z += k0 * sum.z; a0.w += k0 * sum.w;
        a1.x += k1 * sum.x; a1.y += k1 * sum.y; a1.z += k1 * sum.z; a1.w += k1 * sum.w;
    }
    // split to bf16 planes; lane covers cols 4*lane .. 4*lane+3
    uint2 h2, l2;
    split2(make_float2(a0.x, a0.y), h2.x, l2.x);
    split2(make_float2(a0.z, a0.w), h2.y, l2.y);
    reinterpret_cast<uint2*>(c0hi)[(size_t)gw * 32 + lane] = h2;
    reinterpret_cast<uint2*>(c0lo)[(size_t)gw * 32 + lane] = l2;
    split2(make_float2(a1.x, a1.y), h2.x, l2.x);
    split2(make_float2(a1.z, a1.w), h2.y, l2.y);
    reinterpret_cast<uint2*>(c1hi)[(size_t)gw * 32 + lane] = h2;
    reinterpret_cast<uint2*>(c1lo)[(size_t)gw * 32 + lane] = l2;
}

// ---------------- launch ----------------------------------------------------------
extern "C" void kernel_launch(void* const* d_in, const int* in_sizes, int n_in,
                              void* d_out, int out_size) {
    const float* x        = (const float*)d_in[0];
    const int*   edge_src = (const int*)  d_in[1];
    const int*   edge_dst = (const int*)  d_in[2];
    const float* proj_w   = (const float*)d_in[3];
    const float* proj_b   = (const float*)d_in[4];
    const float* basis1   = (const float*)d_in[5];
    const float* coeff1   = (const float*)d_in[6];
    const float* bias1    = (const float*)d_in[7];
    const float* loop1    = (const float*)d_in[8];
    const float* basis2   = (const float*)d_in[9];
    const float* coeff2   = (const float*)d_in[10];
    const float* bias2    = (const float*)d_in[11];
    const float* loop2    = (const float*)d_in[12];
    float* out = (float*)d_out;

    float *h0, *h1, *rdeg;
    int *deg, *off, *cur, *part, *csr;
    __nv_bfloat16 *h0hi, *h0lo, *h1hi, *h1lo, *c0hi, *c0lo, *c1hi, *c1lo;
    __nv_bfloat16 *wthi, *wtlo, *pwhi, *pwlo;
    cudaGetSymbolAddress((void**)&h0,   g_h0);
    cudaGetSymbolAddress((void**)&h1,   g_h1);
    cudaGetSymbolAddress((void**)&h0hi, g_h0hi);
    cudaGetSymbolAddress((void**)&h0lo, g_h0lo);
    cudaGetSymbolAddress((void**)&h1hi, g_h1hi);
    cudaGetSymbolAddress((void**)&h1lo, g_h1lo);
    cudaGetSymbolAddress((void**)&c0hi, g_c0hi);
    cudaGetSymbolAddress((void**)&c0lo, g_c0lo);
    cudaGetSymbolAddress((void**)&c1hi, g_c1hi);
    cudaGetSymbolAddress((void**)&c1lo, g_c1lo);
    cudaGetSymbolAddress((void**)&rdeg, g_rdeg);
    cudaGetSymbolAddress((void**)&deg,  g_deg);
    cudaGetSymbolAddress((void**)&off,  g_off);
    cudaGetSymbolAddress((void**)&cur,  g_cur);
    cudaGetSymbolAddress((void**)&part, g_part);
    cudaGetSymbolAddress((void**)&csr,  g_csr);
    cudaGetSymbolAddress((void**)&wthi, g_wthi);
    cudaGetSymbolAddress((void**)&wtlo, g_wtlo);
    cudaGetSymbolAddress((void**)&pwhi, g_pwhi);
    cudaGetSymbolAddress((void**)&pwlo, g_pwlo);

    cudaFuncSetAttribute((const void*)tc_gemm<false, 1, true,  true>,
                         cudaFuncAttributeMaxDynamicSharedMemorySize, GEMM_SMEM);
    cudaFuncSetAttribute((const void*)tc_gemm<true, 3, false, true>,
                         cudaFuncAttributeMaxDynamicSharedMemorySize, GEMM_SMEM);
    cudaFuncSetAttribute((const void*)tc_gemm<true, 3, false, false>,
                         cudaFuncAttributeMaxDynamicSharedMemorySize, GEMM_SMEM);

    const int grid_n    = (NNODES + 127) / 128;             // 782
    const int scan_blks = (RN + 1023) / 1024;               // 293
    const int wt_blocks = (128 * 384 + 255) / 256;          // 192
    const int pwt_blocks = (128 * 128 + 255) / 256;         // 64

    // ---- CSR build (topology only; reused by both layers) ----
    zero_int_kernel<<<(RN + 255) / 256, 256>>>(deg, RN);
    deg_count_kernel<<<(RE + 255) / 256, 256>>>(edge_dst, deg);
    scan_reduce<<<scan_blks, 256>>>(deg, part, RN);
    scan_partials<<<1, 512>>>(part, scan_blks);
    scan_final<<<scan_blks, 256>>>(deg, part, off, cur, rdeg, RN);
    fill_csr_wt<<<FILL_BLOCKS + pwt_blocks, 256>>>(edge_src, edge_dst, cur, csr,
                                                   proj_w, pwhi, pwlo);

    // ---- projection: h0 = x @ proj_w + proj_b (fp32 + planes) ----
    tc_gemm<false, 1, true, true><<<grid_n, 256, GEMM_SMEM>>>(
        x, nullptr, nullptr, nullptr, nullptr, nullptr, nullptr,
        pwhi, pwlo, proj_b, h0, h0hi, h0lo, NNODES);

    // ---- layer 1 ----
    gather_combo_wt<<<GATHER_BLOCKS + wt_blocks, 256>>>(h0, off, csr, rdeg, coeff1,
                                                        c0hi, c0lo, c1hi, c1lo,
                                                        basis1, loop1, wthi, wtlo);
    tc_gemm<true, 3, false, true><<<grid_n, 256, GEMM_SMEM>>>(
        nullptr, c0hi, c0lo, c1hi, c1lo, h0hi, h0lo,
        wthi, wtlo, bias1, h1, h1hi, h1lo, NNODES);

    // ---- layer 2 ----
    gather_combo_wt<<<GATHER_BLOCKS + wt_blocks, 256>>>(h1, off, csr, rdeg, coeff2,
                                                        c0hi, c0lo, c1hi, c1lo,
                                                        basis2, loop2, wthi, wtlo);
    tc_gemm<true, 3, false, false><<<grid_n, 256, GEMM_SMEM>>>(
        nullptr, c0hi, c0lo, c1hi, c1lo, h1hi, h1lo,
        wthi, wtlo, bias2, out, nullptr, nullptr, NNODES);
}

// round 7
// speedup vs baseline: 1.1228x; 1.1228x over previous
#include <cuda_runtime.h>
#include <cuda_bf16.h>
#include <cstdint>

// Problem constants
#define NNODES 100000
#define DDIM   128
#define RREL   3
#define EEDGES 500000
#define NBASIS 2
#define RN     (RREL * NNODES)
#define RE     (RREL * EEDGES)

// ---------------- scratch (device globals) ----------------------------------
__device__ float g_h0[(size_t)NNODES * DDIM];
__device__ float g_h1[(size_t)NNODES * DDIM];
__device__ float g_c0[(size_t)NNODES * DDIM];
__device__ float g_c1[(size_t)NNODES * DDIM];
__device__ float g_rdeg[RN];
__device__ int   g_deg [RN];
__device__ int   g_off [RN + 1];
__device__ int   g_cur [RN];
__device__ int   g_part[1024];
__device__ int   g_csr [RE];
__device__ __nv_bfloat16 g_wthi[128 * 384];
__device__ __nv_bfloat16 g_wtlo[128 * 384];
__device__ __nv_bfloat16 g_pwhi[128 * 128];
__device__ __nv_bfloat16 g_pwlo[128 * 128];

// ---------------- smem layout for the GEMM -----------------------------------
// A: fp32 [128 x 64], pitch 288 B (72 floats) -> conflict-free LDS.64 frags.
// B: bf16 hi/lo [128 x 64], pitch 144 B -> conflict-free LDS.32 frags.
#define A_PITCH_F 72
#define A_PITCH_BYTES (A_PITCH_F * 4)          // 288
#define A_TILE (128 * A_PITCH_BYTES)           // 36864
#define B_PITCH 144
#define B_TILE (128 * B_PITCH)                 // 18432
#define OFF_A0 0
#define OFF_A1 (A_TILE)
#define OFF_BHI (2 * A_TILE)
#define OFF_BLO (2 * A_TILE + B_TILE)
#define GEMM_SMEM (2 * A_TILE + 2 * B_TILE)    // 110592

__device__ __forceinline__ uint32_t smem_u32(const void* p) {
    uint32_t a;
    asm("{ .reg .u64 t; cvta.to.shared.u64 t, %1; cvt.u32.u64 %0, t; }" : "=r"(a) : "l"(p));
    return a;
}

__device__ __forceinline__ void cp_async16(uint32_t dst, const void* src, uint32_t sz) {
    asm volatile("cp.async.cg.shared.global [%0], [%1], 16, %2;"
                 :: "r"(dst), "l"(src), "r"(sz));
}
#define CP_COMMIT()  asm volatile("cp.async.commit_group;" ::: "memory")
#define CP_WAIT(n)   asm volatile("cp.async.wait_group %0;" :: "n"(n) : "memory")

__device__ __forceinline__ void mma16816(float* c, const uint32_t* a, const uint32_t* b) {
    asm volatile(
        "mma.sync.aligned.m16n8k16.row.col.f32.bf16.bf16.f32 "
        "{%0,%1,%2,%3}, {%4,%5,%6,%7}, {%8,%9}, {%0,%1,%2,%3};\n"
        : "+f"(c[0]), "+f"(c[1]), "+f"(c[2]), "+f"(c[3])
        : "r"(a[0]), "r"(a[1]), "r"(a[2]), "r"(a[3]), "r"(b[0]), "r"(b[1]));
}

// fp32 pair -> packed bf16x2 hi + packed bf16x2 residual(lo). x -> low half.
__device__ __forceinline__ void split2(float2 f, uint32_t& h, uint32_t& l) {
    uint32_t hh;
    asm("cvt.rn.bf16x2.f32 %0, %1, %2;" : "=r"(hh) : "f"(f.y), "f"(f.x));
    float h0 = __uint_as_float(hh << 16);
    float h1 = __uint_as_float(hh & 0xffff0000u);
    asm("cvt.rn.bf16x2.f32 %0, %1, %2;" : "=r"(l) : "f"(f.y - h1), "f"(f.x - h0));
    h = hh;
}

// ---------------- split-bf16 tensor-core GEMM ---------------------------------
// 128 threads = 4 warps, warp grid 2x2, warp tile 64x64 (mt=4, nt=8).
// C[n,o] = act( sum_s sum_k A_s[n,k] * W[s*128+k, o] + bias[o] )
template <bool RELU, int NSEG>
__global__ __launch_bounds__(128, 2)
void tc_gemm(const float* __restrict__ A0, const float* __restrict__ A1,
             const float* __restrict__ A2,
             const __nv_bfloat16* __restrict__ whi, const __nv_bfloat16* __restrict__ wlo,
             const float* __restrict__ bias, float* __restrict__ C, int nrows) {
    extern __shared__ char smem[];
    const uint32_t sbase = smem_u32(smem);
    const int tid  = threadIdx.x;
    const int wid  = tid >> 5;
    const int lane = tid & 31;
    const int wm = wid & 1;          // warp row (2) -> 64 rows each
    const int wn = wid >> 1;         // warp col (2) -> 64 cols each
    const int g  = lane >> 2;        // 0..7
    const int tg = lane & 3;         // 0..3
    const int n0 = blockIdx.x * 128;
    const int KSTRIDE = NSEG * 128;
    const float* Aseg[3] = {A0, A1, A2};
    const int NCHUNK = 2 * NSEG;

    float acc[4][8][4];
#pragma unroll
    for (int mt = 0; mt < 4; mt++)
#pragma unroll
        for (int nt = 0; nt < 8; nt++)
#pragma unroll
            for (int j = 0; j < 4; j++) acc[mt][nt][j] = 0.f;

    auto load_A = [&](int cc) {
        const float* A = Aseg[cc >> 1];
        const int kc = (cc & 1) * 64;
        uint32_t dbase = sbase + ((cc & 1) ? OFF_A1 : OFF_A0);
#pragma unroll
        for (int i = 0; i < 16; ++i) {
            int idx = i * 128 + tid;       // 0..2047 16B transfers
            int row = idx >> 4;
            int q   = idx & 15;
            int n = n0 + row;
            bool valid = (n < nrows);
            const float* src = A + (size_t)(valid ? n : 0) * DDIM + kc + q * 4;
            cp_async16(dbase + row * A_PITCH_BYTES + q * 16, src, valid ? 16u : 0u);
        }
    };

    auto load_B = [&](int cc) {
#pragma unroll
        for (int i = 0; i < 8; ++i) {
            int idx = i * 128 + tid;       // 0..1023 per plane
            int n = idx >> 3;
            int q = idx & 7;
            uint32_t boff = n * B_PITCH + q * 16;
            size_t goff = (size_t)n * KSTRIDE + cc * 64 + q * 8;
            cp_async16(sbase + OFF_BHI + boff, whi + goff, 16);
            cp_async16(sbase + OFF_BLO + boff, wlo + goff, 16);
        }
    };

    const int arow_f = (wm * 64 + g) * A_PITCH_F + 2 * tg;   // float index base
    const int brow   = (wn * 64 + g) * B_PITCH + tg * 4;     // byte offset base

    load_A(0);
    CP_COMMIT();

#pragma unroll 1
    for (int c = 0; c < NCHUNK; ++c) {
        load_B(c);
        CP_COMMIT();
        if (c + 1 < NCHUNK) {
            load_A(c + 1);
            CP_COMMIT();
            CP_WAIT(1);
        } else {
            CP_WAIT(0);
        }
        __syncthreads();

        const char* Ab = smem + ((c & 1) ? OFF_A1 : OFF_A0);

#pragma unroll
        for (int ks = 0; ks < 4; ++ks) {
            uint32_t ahi[4][4], alo[4][4], bfr[8][2];
#pragma unroll
            for (int mt = 0; mt < 4; ++mt) {
                int fb = arow_f + mt * 16 * A_PITCH_F + ks * 16;
                float2 f0 = *reinterpret_cast<const float2*>(Ab + fb * 4);
                float2 f1 = *reinterpret_cast<const float2*>(Ab + (fb + 8 * A_PITCH_F) * 4);
                float2 f2 = *reinterpret_cast<const float2*>(Ab + (fb + 8) * 4);
                float2 f3 = *reinterpret_cast<const float2*>(Ab + (fb + 8 * A_PITCH_F + 8) * 4);
                split2(f0, ahi[mt][0], alo[mt][0]);
                split2(f1, ahi[mt][1], alo[mt][1]);
                split2(f2, ahi[mt][2], alo[mt][2]);
                split2(f3, ahi[mt][3], alo[mt][3]);
            }
#pragma unroll
            for (int nt = 0; nt < 8; ++nt) {
                int bb = brow + nt * (8 * B_PITCH) + ks * 32;
                bfr[nt][0] = *(const uint32_t*)(smem + OFF_BHI + bb);
                bfr[nt][1] = *(const uint32_t*)(smem + OFF_BHI + bb + 16);
            }
#pragma unroll
            for (int mt = 0; mt < 4; ++mt)
#pragma unroll
                for (int nt = 0; nt < 8; ++nt) {
                    mma16816(acc[mt][nt], ahi[mt], bfr[nt]);   // hi*hi
                    mma16816(acc[mt][nt], alo[mt], bfr[nt]);   // lo*hi
                }
#pragma unroll
            for (int nt = 0; nt < 8; ++nt) {
                int bb = brow + nt * (8 * B_PITCH) + ks * 32;
                bfr[nt][0] = *(const uint32_t*)(smem + OFF_BLO + bb);
                bfr[nt][1] = *(const uint32_t*)(smem + OFF_BLO + bb + 16);
            }
#pragma unroll
            for (int mt = 0; mt < 4; ++mt)
#pragma unroll
                for (int nt = 0; nt < 8; ++nt)
                    mma16816(acc[mt][nt], ahi[mt], bfr[nt]);   // hi*lo
        }
        __syncthreads();
    }

    // ---- epilogue: bias + relu, float2 stores ----
#pragma unroll
    for (int nt = 0; nt < 8; ++nt) {
        int col = wn * 64 + nt * 8 + 2 * tg;
        float bz0 = __ldg(bias + col);
        float bz1 = __ldg(bias + col + 1);
#pragma unroll
        for (int mt = 0; mt < 4; ++mt) {
            int row0 = n0 + wm * 64 + mt * 16 + g;
            int row1 = row0 + 8;
            float v0 = acc[mt][nt][0] + bz0, v1 = acc[mt][nt][1] + bz1;
            float v2 = acc[mt][nt][2] + bz0, v3 = acc[mt][nt][3] + bz1;
            if (RELU) {
                v0 = fmaxf(v0, 0.f); v1 = fmaxf(v1, 0.f);
                v2 = fmaxf(v2, 0.f); v3 = fmaxf(v3, 0.f);
            }
            if (row0 < nrows)
                *reinterpret_cast<float2*>(C + (size_t)row0 * DDIM + col) = make_float2(v0, v1);
            if (row1 < nrows)
                *reinterpret_cast<float2*>(C + (size_t)row1 * DDIM + col) = make_float2(v2, v3);
        }
    }
}

// ---------------- CSR construction -------------------------------------------
__global__ void zero_int_kernel(int* p, int n) {
    int i = blockIdx.x * blockDim.x + threadIdx.x;
    if (i < n) p[i] = 0;
}

__global__ void deg_count_kernel(const int* __restrict__ dst, int* __restrict__ deg) {
    int i = blockIdx.x * blockDim.x + threadIdx.x;
    if (i >= RE) return;
    int r = i / EEDGES;
    atomicAdd(&deg[r * NNODES + dst[i]], 1);
}

__global__ void scan_reduce(const int* __restrict__ deg, int* __restrict__ part, int n) {
    __shared__ int sm[256];
    int b = blockIdx.x, t = threadIdx.x;
    int i0 = b * 1024 + t * 4;
    int s = 0;
#pragma unroll
    for (int j = 0; j < 4; ++j) { int i = i0 + j; if (i < n) s += deg[i]; }
    sm[t] = s; __syncthreads();
    for (int st = 128; st > 0; st >>= 1) { if (t < st) sm[t] += sm[t + st]; __syncthreads(); }
    if (t == 0) part[b] = sm[0];
}

__global__ void scan_partials(int* part, int n) {
    __shared__ int sm[512];
    int t = threadIdx.x;
    int v = (t < n) ? part[t] : 0;
    sm[t] = v; __syncthreads();
    for (int s = 1; s < 512; s <<= 1) {
        int add = (t >= s) ? sm[t - s] : 0;
        __syncthreads();
        sm[t] += add;
        __syncthreads();
    }
    if (t < n) part[t] = sm[t] - v;
}

__global__ void scan_final(const int* __restrict__ deg, const int* __restrict__ part,
                           int* __restrict__ off, int* __restrict__ cur,
                           float* __restrict__ rdeg, int n) {
    __shared__ int sm[256];
    int b = blockIdx.x, t = threadIdx.x;
    if (b == 0 && t == 0) off[RN] = RE;
    int i0 = b * 1024 + t * 4;
    int v[4]; int s = 0;
#pragma unroll
    for (int j = 0; j < 4; ++j) { int i = i0 + j; v[j] = (i < n) ? deg[i] : 0; s += v[j]; }
    sm[t] = s; __syncthreads();
    for (int st = 1; st < 256; st <<= 1) {
        int add = (t >= st) ? sm[t - st] : 0;
        __syncthreads();
        sm[t] += add;
        __syncthreads();
    }
    int base = part[b] + sm[t] - s;
#pragma unroll
    for (int j = 0; j < 4; ++j) {
        int i = i0 + j;
        if (i < n) {
            off[i] = base; cur[i] = base; base += v[j];
            rdeg[i] = 1.0f / fmaxf((float)v[j], 1.0f);
        }
    }
}

// fill CSR + build proj weights (extra blocks)
#define FILL_BLOCKS ((RE + 255) / 256)
__global__ void fill_csr_wt(const int* __restrict__ src, const int* __restrict__ dst,
                            int* __restrict__ cur, int* __restrict__ csr,
                            const float* __restrict__ projw,
                            __nv_bfloat16* __restrict__ pwhi, __nv_bfloat16* __restrict__ pwlo) {
    int b = blockIdx.x;
    if (b >= FILL_BLOCKS) {
        int i = (b - FILL_BLOCKS) * 256 + threadIdx.x;   // 128*128
        if (i < 128 * 128) {
            int o = i >> 7;
            int k = i & 127;
            float v = projw[k * DDIM + o];
            __nv_bfloat16 h = __float2bfloat16(v);
            pwhi[i] = h;
            pwlo[i] = __float2bfloat16(v - __bfloat162float(h));
        }
        return;
    }
    int i = b * 256 + threadIdx.x;
    if (i >= RE) return;
    int r = i / EEDGES;
    int slot = atomicAdd(&cur[r * NNODES + dst[i]], 1);
    csr[slot] = src[i];
}

// ---------------- gather-aggregate into fp32 basis combos + layer wt build ----
#define GATHER_BLOCKS ((NNODES * 32 + 255) / 256)
__global__ __launch_bounds__(256)
void gather_combo_wt(const float* __restrict__ h, const int* __restrict__ off,
                     const int* __restrict__ csr, const float* __restrict__ rdeg,
                     const float* __restrict__ coeff,
                     float* __restrict__ c0, float* __restrict__ c1,
                     const float* __restrict__ basis, const float* __restrict__ loopw,
                     __nv_bfloat16* __restrict__ whi, __nv_bfloat16* __restrict__ wlo) {
    int b = blockIdx.x;
    if (b >= GATHER_BLOCKS) {
        int i = (b - GATHER_BLOCKS) * 256 + threadIdx.x;   // 128*384
        if (i < 128 * 384) {
            int o = i / 384;
            int k = i - o * 384;
            int seg = k >> 7;
            int kk = k & 127;
            float v = (seg < 2) ? basis[(size_t)seg * DDIM * DDIM + kk * DDIM + o]
                                : loopw[kk * DDIM + o];
            __nv_bfloat16 hh = __float2bfloat16(v);
            whi[i] = hh;
            wlo[i] = __float2bfloat16(v - __bfloat162float(hh));
        }
        return;
    }
    int gw = (int)(((unsigned)b * 256u + threadIdx.x) >> 5);
    int lane = threadIdx.x & 31;
    if (gw >= NNODES) return;
    float4 a0 = make_float4(0.f, 0.f, 0.f, 0.f);
    float4 a1 = a0;
#pragma unroll
    for (int r = 0; r < RREL; ++r) {
        int base = r * NNODES + gw;
        int s0 = __ldg(off + base), s1 = __ldg(off + base + 1);
        float4 sum = make_float4(0.f, 0.f, 0.f, 0.f);
        int e = s0;
        for (; e + 2 <= s1; e += 2) {
            int sa = __ldg(csr + e), sb = __ldg(csr + e + 1);
            float4 va = *reinterpret_cast<const float4*>(h + (size_t)sa * DDIM + lane * 4);
            float4 vb = *reinterpret_cast<const float4*>(h + (size_t)sb * DDIM + lane * 4);
            sum.x += va.x + vb.x; sum.y += va.y + vb.y;
            sum.z += va.z + vb.z; sum.w += va.w + vb.w;
        }
        if (e < s1) {
            int sa = __ldg(csr + e);
            float4 va = *reinterpret_cast<const float4*>(h + (size_t)sa * DDIM + lane * 4);
            sum.x += va.x; sum.y += va.y; sum.z += va.z; sum.w += va.w;
        }
        float w  = __ldg(rdeg + base);
        float k0 = __ldg(coeff + r * NBASIS)     * w;
        float k1 = __ldg(coeff + r * NBASIS + 1) * w;
        a0.x += k0 * sum.x; a0.y += k0 * sum.y; a0.z += k0 * sum.z; a0.w += k0 * sum.w;
        a1.x += k1 * sum.x; a1.y += k1 * sum.y; a1.z += k1 * sum.z; a1.w += k1 * sum.w;
    }
    *reinterpret_cast<float4*>(c0 + (size_t)gw * DDIM + lane * 4) = a0;
    *reinterpret_cast<float4*>(c1 + (size_t)gw * DDIM + lane * 4) = a1;
}

// ---------------- launch ----------------------------------------------------------
extern "C" void kernel_launch(void* const* d_in, const int* in_sizes, int n_in,
                              void* d_out, int out_size) {
    const float* x        = (const float*)d_in[0];
    const int*   edge_src = (const int*)  d_in[1];
    const int*   edge_dst = (const int*)  d_in[2];
    const float* proj_w   = (const float*)d_in[3];
    const float* proj_b   = (const float*)d_in[4];
    const float* basis1   = (const float*)d_in[5];
    const float* coeff1   = (const float*)d_in[6];
    const float* bias1    = (const float*)d_in[7];
    const float* loop1    = (const float*)d_in[8];
    const float* basis2   = (const float*)d_in[9];
    const float* coeff2   = (const float*)d_in[10];
    const float* bias2    = (const float*)d_in[11];
    const float* loop2    = (const float*)d_in[12];
    float* out = (float*)d_out;

    float *h0, *h1, *c0, *c1, *rdeg;
    int *deg, *off, *cur, *part, *csr;
    __nv_bfloat16 *wthi, *wtlo, *pwhi, *pwlo;
    cudaGetSymbolAddress((void**)&h0,   g_h0);
    cudaGetSymbolAddress((void**)&h1,   g_h1);
    cudaGetSymbolAddress((void**)&c0,   g_c0);
    cudaGetSymbolAddress((void**)&c1,   g_c1);
    cudaGetSymbolAddress((void**)&rdeg, g_rdeg);
    cudaGetSymbolAddress((void**)&deg,  g_deg);
    cudaGetSymbolAddress((void**)&off,  g_off);
    cudaGetSymbolAddress((void**)&cur,  g_cur);
    cudaGetSymbolAddress((void**)&part, g_part);
    cudaGetSymbolAddress((void**)&csr,  g_csr);
    cudaGetSymbolAddress((void**)&wthi, g_wthi);
    cudaGetSymbolAddress((void**)&wtlo, g_wtlo);
    cudaGetSymbolAddress((void**)&pwhi, g_pwhi);
    cudaGetSymbolAddress((void**)&pwlo, g_pwlo);

    cudaFuncSetAttribute(tc_gemm<false, 1>, cudaFuncAttributeMaxDynamicSharedMemorySize, GEMM_SMEM);
    cudaFuncSetAttribute(tc_gemm<true, 3>,  cudaFuncAttributeMaxDynamicSharedMemorySize, GEMM_SMEM);

    const int grid_n     = (NNODES + 127) / 128;             // 782
    const int scan_blks  = (RN + 1023) / 1024;               // 293
    const int wt_blocks  = (128 * 384 + 255) / 256;          // 192
    const int pwt_blocks = (128 * 128 + 255) / 256;          // 64

    // ---- CSR build (topology only; reused by both layers) ----
    zero_int_kernel<<<(RN + 255) / 256, 256>>>(deg, RN);
    deg_count_kernel<<<(RE + 255) / 256, 256>>>(edge_dst, deg);
    scan_reduce<<<scan_blks, 256>>>(deg, part, RN);
    scan_partials<<<1, 512>>>(part, scan_blks);
    scan_final<<<scan_blks, 256>>>(deg, part, off, cur, rdeg, RN);
    fill_csr_wt<<<FILL_BLOCKS + pwt_blocks, 256>>>(edge_src, edge_dst, cur, csr,
                                                   proj_w, pwhi, pwlo);

    // ---- projection: h0 = x @ proj_w + proj_b ----
    tc_gemm<false, 1><<<grid_n, 128, GEMM_SMEM>>>(x, nullptr, nullptr,
                                                  pwhi, pwlo, proj_b, h0, NNODES);

    // ---- layer 1 ----
    gather_combo_wt<<<GATHER_BLOCKS + wt_blocks, 256>>>(h0, off, csr, rdeg, coeff1,
                                                        c0, c1, basis1, loop1, wthi, wtlo);
    tc_gemm<true, 3><<<grid_n, 128, GEMM_SMEM>>>(c0, c1, h0,
                                                 wthi, wtlo, bias1, h1, NNODES);

    // ---- layer 2 ----
    gather_combo_wt<<<GATHER_BLOCKS + wt_blocks, 256>>>(h1, off, csr, rdeg, coeff2,
                                                        c0, c1, basis2, loop2, wthi, wtlo);
    tc_gemm<true, 3><<<grid_n, 128, GEMM_SMEM>>>(c0, c1, h1,
                                                 wthi, wtlo, bias2, out, NNODES);
}

// round 8
// speedup vs baseline: 1.4673x; 1.3069x over previous
#include <cuda_runtime.h>
#include <cuda_fp16.h>
#include <cstdint>

// Problem constants
#define NNODES 100000
#define DDIM   128
#define RREL   3
#define EEDGES 500000
#define NBASIS 2
#define RN     (RREL * NNODES)
#define RE     (RREL * EEDGES)

// ---------------- scratch (device globals) ----------------------------------
__device__ __half g_h0f[(size_t)NNODES * DDIM];   // activations, fp16
__device__ __half g_h1f[(size_t)NNODES * DDIM];
__device__ __half g_c0f[(size_t)NNODES * DDIM];   // basis combos, fp16
__device__ __half g_c1f[(size_t)NNODES * DDIM];
__device__ float g_rdeg[RN];
__device__ int   g_deg [RN];
__device__ int   g_off [RN + 1];
__device__ int   g_cur [RN];
__device__ int   g_part[1024];
__device__ int   g_csr [RE];
__device__ __half g_wthi[128 * 384];   // layer weights [o][k], fp16 hi
__device__ __half g_wtlo[128 * 384];   // fp16 residual
__device__ __half g_pwhi[128 * 128];   // proj weights [o][k]
__device__ __half g_pwlo[128 * 128];

// ---------------- smem geometry -----------------------------------------------
// fp16 tiles ([128 x 64], pitch 144 B) for A (non-proj) and B hi/lo.
// proj stages A as fp32 ([128 x 64], pitch 288 B).
#define B_PITCH 144
#define B_TILE (128 * B_PITCH)                 // 18432
#define A_PITCH_F 72
#define A_TILE_F32 (128 * A_PITCH_F * 4)       // 36864

__device__ __forceinline__ uint32_t smem_u32(const void* p) {
    uint32_t a;
    asm("{ .reg .u64 t; cvta.to.shared.u64 t, %1; cvt.u32.u64 %0, t; }" : "=r"(a) : "l"(p));
    return a;
}

__device__ __forceinline__ void cp_async16(uint32_t dst, const void* src, uint32_t sz) {
    asm volatile("cp.async.cg.shared.global [%0], [%1], 16, %2;"
                 :: "r"(dst), "l"(src), "r"(sz));
}
#define CP_COMMIT()  asm volatile("cp.async.commit_group;" ::: "memory")
#define CP_WAIT(n)   asm volatile("cp.async.wait_group %0;" :: "n"(n) : "memory")

__device__ __forceinline__ void mma16816h(float* c, const uint32_t* a, const uint32_t* b) {
    asm volatile(
        "mma.sync.aligned.m16n8k16.row.col.f32.f16.f16.f32 "
        "{%0,%1,%2,%3}, {%4,%5,%6,%7}, {%8,%9}, {%0,%1,%2,%3};\n"
        : "+f"(c[0]), "+f"(c[1]), "+f"(c[2]), "+f"(c[3])
        : "r"(a[0]), "r"(a[1]), "r"(a[2]), "r"(a[3]), "r"(b[0]), "r"(b[1]));
}

// pack two fp32 -> f16x2 (x -> low half)
__device__ __forceinline__ uint32_t pack_f16x2(float2 f) {
    uint32_t r;
    asm("cvt.rn.f16x2.f32 %0, %1, %2;" : "=r"(r) : "f"(f.y), "f"(f.x));
    return r;
}

// ---------------- fp16 tensor-core GEMM (2-product W-split) -------------------
// 128 threads = 4 warps, warp grid 2x2, warp tile 64x64 (mt=4, nt=8).
// C[n,o] = act( sum_s sum_k A_s[n,k] * W[s*128+k, o] + bias[o] )
// F32A: A = one fp32 segment (proj); converts to fp16 in-loop. NSEG must be 1.
// OUTF16: write fp16 Cf; else fp32 C.
template <bool RELU, int NSEG, bool F32A, bool OUTF16>
__global__ __launch_bounds__(128, 2)
void tc_gemm(const float* __restrict__ Af,
             const __half* __restrict__ A0, const __half* __restrict__ A1,
             const __half* __restrict__ A2,
             const __half* __restrict__ whi, const __half* __restrict__ wlo,
             const float* __restrict__ bias, float* __restrict__ C,
             __half* __restrict__ Cf, int nrows) {
    extern __shared__ char smem[];
    constexpr int ATILE   = F32A ? A_TILE_F32 : B_TILE;
    constexpr int OFF_A1_ = ATILE;
    constexpr int OFF_BH  = 2 * ATILE;
    constexpr int OFF_BL  = 2 * ATILE + B_TILE;
    const uint32_t sbase = smem_u32(smem);
    const int tid  = threadIdx.x;
    const int wid  = tid >> 5;
    const int lane = tid & 31;
    const int wm = wid & 1;          // warp row (2) -> 64 rows
    const int wn = wid >> 1;         // warp col (2) -> 64 cols
    const int g  = lane >> 2;
    const int tg = lane & 3;
    const int n0 = blockIdx.x * 128;
    const int KSTRIDE = NSEG * 128;
    const __half* Aseg[3] = {A0, A1, A2};
    const int NCHUNK = 2 * NSEG;

    float acc[4][8][4];
#pragma unroll
    for (int mt = 0; mt < 4; mt++)
#pragma unroll
        for (int nt = 0; nt < 8; nt++)
#pragma unroll
            for (int j = 0; j < 4; j++) acc[mt][nt][j] = 0.f;

    auto load_A = [&](int cc) {
        const int kc = (cc & 1) * 64;
        uint32_t dbase = sbase + ((cc & 1) ? OFF_A1_ : 0);
        if constexpr (F32A) {
#pragma unroll
            for (int i = 0; i < 16; ++i) {
                int idx = i * 128 + tid;           // 2048 x 16B
                int row = idx >> 4;
                int q   = idx & 15;
                int n = n0 + row;
                bool valid = (n < nrows);
                const float* src = Af + (size_t)(valid ? n : 0) * DDIM + kc + q * 4;
                cp_async16(dbase + row * (A_PITCH_F * 4) + q * 16, src, valid ? 16u : 0u);
            }
        } else {
            const __half* A = Aseg[cc >> 1];
#pragma unroll
            for (int i = 0; i < 8; ++i) {
                int idx = i * 128 + tid;           // 1024 x 16B
                int row = idx >> 3;
                int q   = idx & 7;
                int n = n0 + row;
                bool valid = (n < nrows);
                const __half* src = A + (size_t)(valid ? n : 0) * DDIM + kc + q * 8;
                cp_async16(dbase + row * B_PITCH + q * 16, src, valid ? 16u : 0u);
            }
        }
    };

    auto load_B = [&](int cc) {
#pragma unroll
        for (int i = 0; i < 8; ++i) {
            int idx = i * 128 + tid;               // 1024 per plane
            int n = idx >> 3;
            int q = idx & 7;
            uint32_t boff = n * B_PITCH + q * 16;
            size_t goff = (size_t)n * KSTRIDE + cc * 64 + q * 8;
            cp_async16(sbase + OFF_BH + boff, whi + goff, 16);
            cp_async16(sbase + OFF_BL + boff, wlo + goff, 16);
        }
    };

    const int arow_f = (wm * 64 + g) * A_PITCH_F + 2 * tg;   // fp32 path (float idx)
    const int arow_b = (wm * 64 + g) * B_PITCH + tg * 4;     // fp16 path (byte)
    const int brow   = (wn * 64 + g) * B_PITCH + tg * 4;

    load_A(0);
    CP_COMMIT();

#pragma unroll 1
    for (int c = 0; c < NCHUNK; ++c) {
        load_B(c);
        CP_COMMIT();
        if (c + 1 < NCHUNK) {
            load_A(c + 1);
            CP_COMMIT();
            CP_WAIT(1);
        } else {
            CP_WAIT(0);
        }
        __syncthreads();

        const char* Ab = smem + ((c & 1) ? OFF_A1_ : 0);

#pragma unroll
        for (int ks = 0; ks < 4; ++ks) {
            uint32_t a[4][4], bfr[8][2];
            if constexpr (F32A) {
#pragma unroll
                for (int mt = 0; mt < 4; ++mt) {
                    int fb = arow_f + mt * 16 * A_PITCH_F + ks * 16;
                    float2 f0 = *reinterpret_cast<const float2*>(Ab + fb * 4);
                    float2 f1 = *reinterpret_cast<const float2*>(Ab + (fb + 8 * A_PITCH_F) * 4);
                    float2 f2 = *reinterpret_cast<const float2*>(Ab + (fb + 8) * 4);
                    float2 f3 = *reinterpret_cast<const float2*>(Ab + (fb + 8 * A_PITCH_F + 8) * 4);
                    a[mt][0] = pack_f16x2(f0);
                    a[mt][1] = pack_f16x2(f1);
                    a[mt][2] = pack_f16x2(f2);
                    a[mt][3] = pack_f16x2(f3);
                }
            } else {
#pragma unroll
                for (int mt = 0; mt < 4; ++mt) {
                    int bb = arow_b + mt * 16 * B_PITCH + ks * 32;
                    a[mt][0] = *(const uint32_t*)(Ab + bb);
                    a[mt][1] = *(const uint32_t*)(Ab + bb + 8 * B_PITCH);
                    a[mt][2] = *(const uint32_t*)(Ab + bb + 16);
                    a[mt][3] = *(const uint32_t*)(Ab + bb + 8 * B_PITCH + 16);
                }
            }
#pragma unroll
            for (int nt = 0; nt < 8; ++nt) {
                int bb = brow + nt * (8 * B_PITCH) + ks * 32;
                bfr[nt][0] = *(const uint32_t*)(smem + OFF_BH + bb);
                bfr[nt][1] = *(const uint32_t*)(smem + OFF_BH + bb + 16);
            }
#pragma unroll
            for (int mt = 0; mt < 4; ++mt)
#pragma unroll
                for (int nt = 0; nt < 8; ++nt)
                    mma16816h(acc[mt][nt], a[mt], bfr[nt]);    // A * Whi
#pragma unroll
            for (int nt = 0; nt < 8; ++nt) {
                int bb = brow + nt * (8 * B_PITCH) + ks * 32;
                bfr[nt][0] = *(const uint32_t*)(smem + OFF_BL + bb);
                bfr[nt][1] = *(const uint32_t*)(smem + OFF_BL + bb + 16);
            }
#pragma unroll
            for (int mt = 0; mt < 4; ++mt)
#pragma unroll
                for (int nt = 0; nt < 8; ++nt)
                    mma16816h(acc[mt][nt], a[mt], bfr[nt]);    // A * Wlo
        }
        __syncthreads();
    }

    // ---- epilogue: bias + relu ----
#pragma unroll
    for (int nt = 0; nt < 8; ++nt) {
        int col = wn * 64 + nt * 8 + 2 * tg;
        float bz0 = __ldg(bias + col);
        float bz1 = __ldg(bias + col + 1);
#pragma unroll
        for (int mt = 0; mt < 4; ++mt) {
            int row0 = n0 + wm * 64 + mt * 16 + g;
            int row1 = row0 + 8;
            float v0 = acc[mt][nt][0] + bz0, v1 = acc[mt][nt][1] + bz1;
            float v2 = acc[mt][nt][2] + bz0, v3 = acc[mt][nt][3] + bz1;
            if (RELU) {
                v0 = fmaxf(v0, 0.f); v1 = fmaxf(v1, 0.f);
                v2 = fmaxf(v2, 0.f); v3 = fmaxf(v3, 0.f);
            }
            if (row0 < nrows) {
                if constexpr (OUTF16)
                    *reinterpret_cast<uint32_t*>(Cf + (size_t)row0 * DDIM + col) =
                        pack_f16x2(make_float2(v0, v1));
                else
                    *reinterpret_cast<float2*>(C + (size_t)row0 * DDIM + col) = make_float2(v0, v1);
            }
            if (row1 < nrows) {
                if constexpr (OUTF16)
                    *reinterpret_cast<uint32_t*>(Cf + (size_t)row1 * DDIM + col) =
                        pack_f16x2(make_float2(v2, v3));
                else
                    *reinterpret_cast<float2*>(C + (size_t)row1 * DDIM + col) = make_float2(v2, v3);
            }
        }
    }
}

// ---------------- CSR construction -------------------------------------------
__global__ void zero_int_kernel(int* p, int n) {
    int i = blockIdx.x * blockDim.x + threadIdx.x;
    if (i < n) p[i] = 0;
}

__global__ void deg_count_kernel(const int* __restrict__ dst, int* __restrict__ deg) {
    int i = blockIdx.x * blockDim.x + threadIdx.x;
    if (i >= RE) return;
    int r = i / EEDGES;
    atomicAdd(&deg[r * NNODES + dst[i]], 1);
}

__global__ void scan_reduce(const int* __restrict__ deg, int* __restrict__ part, int n) {
    __shared__ int sm[256];
    int b = blockIdx.x, t = threadIdx.x;
    int i0 = b * 1024 + t * 4;
    int s = 0;
#pragma unroll
    for (int j = 0; j < 4; ++j) { int i = i0 + j; if (i < n) s += deg[i]; }
    sm[t] = s; __syncthreads();
    for (int st = 128; st > 0; st >>= 1) { if (t < st) sm[t] += sm[t + st]; __syncthreads(); }
    if (t == 0) part[b] = sm[0];
}

__global__ void scan_partials(int* part, int n) {
    __shared__ int sm[512];
    int t = threadIdx.x;
    int v = (t < n) ? part[t] : 0;
    sm[t] = v; __syncthreads();
    for (int s = 1; s < 512; s <<= 1) {
        int add = (t >= s) ? sm[t - s] : 0;
        __syncthreads();
        sm[t] += add;
        __syncthreads();
    }
    if (t < n) part[t] = sm[t] - v;
}

__global__ void scan_final(const int* __restrict__ deg, const int* __restrict__ part,
                           int* __restrict__ off, int* __restrict__ cur,
                           float* __restrict__ rdeg, int n) {
    __shared__ int sm[256];
    int b = blockIdx.x, t = threadIdx.x;
    if (b == 0 && t == 0) off[RN] = RE;
    int i0 = b * 1024 + t * 4;
    int v[4]; int s = 0;
#pragma unroll
    for (int j = 0; j < 4; ++j) { int i = i0 + j; v[j] = (i < n) ? deg[i] : 0; s += v[j]; }
    sm[t] = s; __syncthreads();
    for (int st = 1; st < 256; st <<= 1) {
        int add = (t >= st) ? sm[t - st] : 0;
        __syncthreads();
        sm[t] += add;
        __syncthreads();
    }
    int base = part[b] + sm[t] - s;
#pragma unroll
    for (int j = 0; j < 4; ++j) {
        int i = i0 + j;
        if (i < n) {
            off[i] = base; cur[i] = base; base += v[j];
            rdeg[i] = 1.0f / fmaxf((float)v[j], 1.0f);
        }
    }
}

// fill CSR + build proj weights (fp16 hi/lo) in extra blocks
#define FILL_BLOCKS ((RE + 255) / 256)
__global__ void fill_csr_wt(const int* __restrict__ src, const int* __restrict__ dst,
                            int* __restrict__ cur, int* __restrict__ csr,
                            const float* __restrict__ projw,
                            __half* __restrict__ pwhi, __half* __restrict__ pwlo) {
    int b = blockIdx.x;
    if (b >= FILL_BLOCKS) {
        int i = (b - FILL_BLOCKS) * 256 + threadIdx.x;   // 128*128
        if (i < 128 * 128) {
            int o = i >> 7;
            int k = i & 127;
            float v = projw[k * DDIM + o];
            __half h = __float2half_rn(v);
            pwhi[i] = h;
            pwlo[i] = __float2half_rn(v - __half2float(h));
        }
        return;
    }
    int i = b * 256 + threadIdx.x;
    if (i >= RE) return;
    int r = i / EEDGES;
    int slot = atomicAdd(&cur[r * NNODES + dst[i]], 1);
    csr[slot] = src[i];
}

// ---------------- gather-aggregate (fp16 h -> fp16 combos) + layer wt build ----
#define GATHER_BLOCKS ((NNODES * 32 + 255) / 256)
__global__ __launch_bounds__(256)
void gather_combo_wt(const __half* __restrict__ h, const int* __restrict__ off,
                     const int* __restrict__ csr, const float* __restrict__ rdeg,
                     const float* __restrict__ coeff,
                     __half* __restrict__ c0, __half* __restrict__ c1,
                     const float* __restrict__ basis, const float* __restrict__ loopw,
                     __half* __restrict__ whi, __half* __restrict__ wlo) {
    int b = blockIdx.x;
    if (b >= GATHER_BLOCKS) {
        int i = (b - GATHER_BLOCKS) * 256 + threadIdx.x;   // 128*384
        if (i < 128 * 384) {
            int o = i / 384;
            int k = i - o * 384;
            int seg = k >> 7;
            int kk = k & 127;
            float v = (seg < 2) ? basis[(size_t)seg * DDIM * DDIM + kk * DDIM + o]
                                : loopw[kk * DDIM + o];
            __half hh = __float2half_rn(v);
            whi[i] = hh;
            wlo[i] = __float2half_rn(v - __half2float(hh));
        }
        return;
    }
    int gw = (int)(((unsigned)b * 256u + threadIdx.x) >> 5);
    int lane = threadIdx.x & 31;
    if (gw >= NNODES) return;
    float4 a0 = make_float4(0.f, 0.f, 0.f, 0.f);
    float4 a1 = a0;
#pragma unroll
    for (int r = 0; r < RREL; ++r) {
        int base = r * NNODES + gw;
        int s0 = __ldg(off + base), s1 = __ldg(off + base + 1);
        float4 sum = make_float4(0.f, 0.f, 0.f, 0.f);
        int e = s0;
        for (; e + 2 <= s1; e += 2) {
            int sa = __ldg(csr + e), sb = __ldg(csr + e + 1);
            uint2 ua = *reinterpret_cast<const uint2*>(h + (size_t)sa * DDIM + lane * 4);
            uint2 ub = *reinterpret_cast<const uint2*>(h + (size_t)sb * DDIM + lane * 4);
            float2 fa0 = __half22float2(*reinterpret_cast<__half2*>(&ua.x));
            float2 fa1 = __half22float2(*reinterpret_cast<__half2*>(&ua.y));
            float2 fb0 = __half22float2(*reinterpret_cast<__half2*>(&ub.x));
            float2 fb1 = __half22float2(*reinterpret_cast<__half2*>(&ub.y));
            sum.x += fa0.x + fb0.x; sum.y += fa0.y + fb0.y;
            sum.z += fa1.x + fb1.x; sum.w += fa1.y + fb1.y;
        }
        if (e < s1) {
            int sa = __ldg(csr + e);
            uint2 ua = *reinterpret_cast<const uint2*>(h + (size_t)sa * DDIM + lane * 4);
            float2 fa0 = __half22float2(*reinterpret_cast<__half2*>(&ua.x));
            float2 fa1 = __half22float2(*reinterpret_cast<__half2*>(&ua.y));
            sum.x += fa0.x; sum.y += fa0.y; sum.z += fa1.x; sum.w += fa1.y;
        }
        float w  = __ldg(rdeg + base);
        float k0 = __ldg(coeff + r * NBASIS)     * w;
        float k1 = __ldg(coeff + r * NBASIS + 1) * w;
        a0.x += k0 * sum.x; a0.y += k0 * sum.y; a0.z += k0 * sum.z; a0.w += k0 * sum.w;
        a1.x += k1 * sum.x; a1.y += k1 * sum.y; a1.z += k1 * sum.z; a1.w += k1 * sum.w;
    }
    uint2 o0, o1;
    o0.x = pack_f16x2(make_float2(a0.x, a0.y));
    o0.y = pack_f16x2(make_float2(a0.z, a0.w));
    o1.x = pack_f16x2(make_float2(a1.x, a1.y));
    o1.y = pack_f16x2(make_float2(a1.z, a1.w));
    *reinterpret_cast<uint2*>(c0 + (size_t)gw * DDIM + lane * 4) = o0;
    *reinterpret_cast<uint2*>(c1 + (size_t)gw * DDIM + lane * 4) = o1;
}

// ---------------- launch ----------------------------------------------------------
extern "C" void kernel_launch(void* const* d_in, const int* in_sizes, int n_in,
                              void* d_out, int out_size) {
    const float* x        = (const float*)d_in[0];
    const int*   edge_src = (const int*)  d_in[1];
    const int*   edge_dst = (const int*)  d_in[2];
    const float* proj_w   = (const float*)d_in[3];
    const float* proj_b   = (const float*)d_in[4];
    const float* basis1   = (const float*)d_in[5];
    const float* coeff1   = (const float*)d_in[6];
    const float* bias1    = (const float*)d_in[7];
    const float* loop1    = (const float*)d_in[8];
    const float* basis2   = (const float*)d_in[9];
    const float* coeff2   = (const float*)d_in[10];
    const float* bias2    = (const float*)d_in[11];
    const float* loop2    = (const float*)d_in[12];
    float* out = (float*)d_out;

    float *rdeg;
    int *deg, *off, *cur, *part, *csr;
    __half *h0f, *h1f, *c0f, *c1f, *wthi, *wtlo, *pwhi, *pwlo;
    cudaGetSymbolAddress((void**)&h0f,  g_h0f);
    cudaGetSymbolAddress((void**)&h1f,  g_h1f);
    cudaGetSymbolAddress((void**)&c0f,  g_c0f);
    cudaGetSymbolAddress((void**)&c1f,  g_c1f);
    cudaGetSymbolAddress((void**)&rdeg, g_rdeg);
    cudaGetSymbolAddress((void**)&deg,  g_deg);
    cudaGetSymbolAddress((void**)&off,  g_off);
    cudaGetSymbolAddress((void**)&cur,  g_cur);
    cudaGetSymbolAddress((void**)&part, g_part);
    cudaGetSymbolAddress((void**)&csr,  g_csr);
    cudaGetSymbolAddress((void**)&wthi, g_wthi);
    cudaGetSymbolAddress((void**)&wtlo, g_wtlo);
    cudaGetSymbolAddress((void**)&pwhi, g_pwhi);
    cudaGetSymbolAddress((void**)&pwlo, g_pwlo);

    const int SMEM_PROJ  = 2 * A_TILE_F32 + 2 * B_TILE;   // 110592
    const int SMEM_LAYER = 4 * B_TILE;                    // 73728

    cudaFuncSetAttribute(tc_gemm<false, 1, true,  true>,
                         cudaFuncAttributeMaxDynamicSharedMemorySize, SMEM_PROJ);
    cudaFuncSetAttribute(tc_gemm<true, 3, false, true>,
                         cudaFuncAttributeMaxDynamicSharedMemorySize, SMEM_LAYER);
    cudaFuncSetAttribute(tc_gemm<true, 3, false, false>,
                         cudaFuncAttributeMaxDynamicSharedMemorySize, SMEM_LAYER);

    const int grid_n     = (NNODES + 127) / 128;             // 782
    const int scan_blks  = (RN + 1023) / 1024;               // 293
    const int wt_blocks  = (128 * 384 + 255) / 256;          // 192
    const int pwt_blocks = (128 * 128 + 255) / 256;          // 64

    // ---- CSR build (topology only; reused by both layers) ----
    zero_int_kernel<<<(RN + 255) / 256, 256>>>(deg, RN);
    deg_count_kernel<<<(RE + 255) / 256, 256>>>(edge_dst, deg);
    scan_reduce<<<scan_blks, 256>>>(deg, part, RN);
    scan_partials<<<1, 512>>>(part, scan_blks);
    scan_final<<<scan_blks, 256>>>(deg, part, off, cur, rdeg, RN);
    fill_csr_wt<<<FILL_BLOCKS + pwt_blocks, 256>>>(edge_src, edge_dst, cur, csr,
                                                   proj_w, pwhi, pwlo);

    // ---- projection: h0f = fp16(x @ proj_w + proj_b) ----
    tc_gemm<false, 1, true, true><<<grid_n, 128, SMEM_PROJ>>>(
        x, nullptr, nullptr, nullptr, pwhi, pwlo, proj_b, nullptr, h0f, NNODES);

    // ---- layer 1 ----
    gather_combo_wt<<<GATHER_BLOCKS + wt_blocks, 256>>>(h0f, off, csr, rdeg, coeff1,
                                                        c0f, c1f, basis1, loop1, wthi, wtlo);
    tc_gemm<true, 3, false, true><<<grid_n, 128, SMEM_LAYER>>>(
        nullptr, c0f, c1f, h0f, wthi, wtlo, bias1, nullptr, h1f, NNODES);

    // ---- layer 2 ----
    gather_combo_wt<<<GATHER_BLOCKS + wt_blocks, 256>>>(h1f, off, csr, rdeg, coeff2,
                                                        c0f, c1f, basis2, loop2, wthi, wtlo);
    tc_gemm<true, 3, false, false><<<grid_n, 128, SMEM_LAYER>>>(
        nullptr, c0f, c1f, h1f, wthi, wtlo, bias2, out, nullptr, NNODES);
}